// round 1
// baseline (speedup 1.0000x reference)
#include <cuda_runtime.h>
#include <math.h>

#define N_NODES 16384
#define F_DIM   256
#define H_DIM   512
#define NPG     64
#define NGRAPH  256
#define MAXDEG  512          // T2 has MAXDEG+1 rows

// ---------------- static device scratch (no allocations allowed) ----------------
__device__ float g_Wc[F_DIM * H_DIM];            // W_feat @ W1
__device__ float g_bconst[H_DIM];                // b_feat @ W1 + b_out
__device__ float g_T2[(MAXDEG + 1) * H_DIM];     // PE(d) @ W2
__device__ float g_T4[(NPG + 1) * H_DIM];        // pe_table @ W4
__device__ float g_pe[N_NODES * H_DIM];          // PE(node index)
__device__ float g_add[N_NODES * H_DIM];         // per-node additive vector
__device__ unsigned long long g_adj[N_NODES];    // 64-bit adjacency row per node
__device__ int g_deg[N_NODES];
__device__ unsigned char g_hist[N_NODES * (NPG + 1)];
__device__ float g_invhi[H_DIM / 2];
__device__ float g_invlo[H_DIM / 2];

// ---------------- accurate PE: sin/cos(pos / 10000^(2k/512)) ----------------
__global__ void k_invdiv() {
    int k = threadIdx.x;
    if (k < H_DIM / 2) {
        double v = exp(-(double)k * (9.210340371976184 / 256.0)); // 1/div_k
        float hi = (float)v;
        g_invhi[k] = hi;
        g_invlo[k] = (float)(v - (double)hi);
    }
}

__device__ __forceinline__ void pe_sincos(float pos, int k, float* s, float* c) {
    float hi = g_invhi[k], lo = g_invlo[k];
    float p  = pos * hi;
    float e  = fmaf(pos, hi, -p);       // exact residual of pos*hi
    float al = fmaf(pos, lo, e);        // low-order part of the angle
    const float I2PI = 0.15915494309189535f;
    const float P2H  = 6.28318548202514648f;   // float(2*pi)
    const float P2L  = -1.7484855e-7f;         // 2*pi - P2H
    float q = rintf(p * I2PI);
    float r = fmaf(-q, P2H, p);
    r = fmaf(-q, P2L, r);
    r += al;
    sincosf(r, s, c);
}

// ---------------- init + graph build ----------------
__global__ void k_init() {
    int i = blockIdx.x * blockDim.x + threadIdx.x;
    if (i < N_NODES) { g_deg[i] = 0; g_adj[i] = 0ull; }
}

__global__ void k_edges(const int* __restrict__ ei, int E) {
    int e = blockIdx.x * blockDim.x + threadIdx.x;
    if (e >= E) return;
    int u = ei[e], v = ei[E + e];
    atomicAdd(&g_deg[u], 1);
    atomicAdd(&g_deg[v], 1);
    atomicOr(&g_adj[u], 1ull << (v & 63));
    atomicOr(&g_adj[v], 1ull << (u & 63));
}

// ---------------- Wc = W_feat @ W1 ; bconst = b_feat @ W1 + b_out ----------------
__global__ void k_wc(const float* __restrict__ Wf, const float* __restrict__ Wout,
                     const float* __restrict__ bf, const float* __restrict__ bo) {
    __shared__ float a_sh[8][H_DIM];
    int o = threadIdx.x;  // 0..511
    if (blockIdx.x < 32) {
        int f0 = blockIdx.x * 8;
        #pragma unroll
        for (int r = 0; r < 8; r++) a_sh[r][o] = Wf[(f0 + r) * H_DIM + o];
        __syncthreads();
        float acc[8] = {0, 0, 0, 0, 0, 0, 0, 0};
        for (int h = 0; h < H_DIM; h++) {
            float w = Wout[h * H_DIM + o];   // W1 row h
            #pragma unroll
            for (int r = 0; r < 8; r++) acc[r] = fmaf(a_sh[r][h], w, acc[r]);
        }
        #pragma unroll
        for (int r = 0; r < 8; r++) g_Wc[(f0 + r) * H_DIM + o] = acc[r];
    } else {
        a_sh[0][o] = bf[o];
        __syncthreads();
        float acc = bo[o];
        for (int h = 0; h < H_DIM; h++) acc = fmaf(a_sh[0][h], Wout[h * H_DIM + o], acc);
        g_bconst[o] = acc;
    }
}

// ---------------- T2 = PE(d)@W2 (513 rows), T4 = pe_table@W4 (65 rows) ----------------
__global__ void k_tables(const float* __restrict__ Wout) {
    __shared__ float pe_sh[8][H_DIM];
    int o = threadIdx.x;
    bool isT2 = blockIdx.x < 65;
    int row0 = isT2 ? blockIdx.x * 8 : (blockIdx.x - 65) * 8;
    int nrows = isT2 ? (MAXDEG + 1) : (NPG + 1);
    const float* W = Wout + (isT2 ? 512 * H_DIM : 1536 * H_DIM);
    float* T = isT2 ? g_T2 : g_T4;

    for (int t = o; t < 8 * 256; t += 512) {
        int r = t >> 8, k = t & 255;
        if (row0 + r < nrows) {
            float s, c;
            pe_sincos((float)(row0 + r), k, &s, &c);
            pe_sh[r][2 * k]     = s;
            pe_sh[r][2 * k + 1] = c;
        } else {
            pe_sh[r][2 * k] = 0.f; pe_sh[r][2 * k + 1] = 0.f;
        }
    }
    __syncthreads();
    float acc[8] = {0, 0, 0, 0, 0, 0, 0, 0};
    for (int h = 0; h < H_DIM; h++) {
        float w = W[h * H_DIM + o];
        #pragma unroll
        for (int r = 0; r < 8; r++) acc[r] = fmaf(pe_sh[r][h], w, acc[r]);
    }
    #pragma unroll
    for (int r = 0; r < 8; r++)
        if (row0 + r < nrows) T[(row0 + r) * H_DIM + o] = acc[r];
}

// ---------------- PE(node index) buffer ----------------
__global__ void k_pe() {
    int i = blockIdx.x;
    int k = threadIdx.x;  // 0..255
    float s, c;
    pe_sincos((float)i, k, &s, &c);
    ((float2*)(g_pe + i * H_DIM))[k] = make_float2(s, c);
}

// ---------------- bit-parallel all-pairs BFS -> hop-distance histogram ----------------
__global__ void k_bfs() {
    __shared__ unsigned long long adj_sh[NPG];
    int g = blockIdx.x;
    int s = threadIdx.x;
    adj_sh[s] = g_adj[g * NPG + s];
    __syncthreads();

    unsigned long long reach = 1ull << s;
    unsigned long long frontier = reach;
    unsigned char cnt[NPG + 1];
    #pragma unroll
    for (int v = 0; v <= NPG; v++) cnt[v] = 0;
    cnt[0] = 1;
    int maxfin = 0;
    for (int k = 1; k < NPG; k++) {
        unsigned long long nr = 0, f = frontier;
        while (f) {
            int j = __ffsll((long long)f) - 1;
            f &= f - 1;
            nr |= adj_sh[j];
        }
        unsigned long long nxt = nr & ~reach;
        if (!nxt) break;
        cnt[k] = (unsigned char)__popcll(nxt);
        maxfin = k;
        reach |= nxt;
        frontier = nxt;
    }
    int rem = NPG - __popcll(reach);           // unreachable -> maxfin+1 (matches ref)
    cnt[maxfin + 1] = (unsigned char)(cnt[maxfin + 1] + rem);

    unsigned char* h = g_hist + (g * NPG + s) * (NPG + 1);
    #pragma unroll
    for (int v = 0; v <= NPG; v++) h[v] = cnt[v];
}

// ---------------- additive vector: T2[deg] + bconst + (1/64) * hist . T4 ----------------
__global__ void k_add() {
    __shared__ int   vlist[NPG + 1];
    __shared__ float clist[NPG + 1];
    __shared__ int   nnz, sdeg;
    int i = blockIdx.x, tid = threadIdx.x;
    if (tid == 0) {
        const unsigned char* h = g_hist + i * (NPG + 1);
        int m = 0;
        for (int v = 0; v <= NPG; v++) {
            int c = h[v];
            if (c) { vlist[m] = v; clist[m] = (float)c * (1.0f / 64.0f); m++; }
        }
        nnz = m;
        int d = g_deg[i];
        sdeg = d > MAXDEG ? MAXDEG : d;
    }
    __syncthreads();
    int d = sdeg, m = nnz;
    for (int c0 = tid; c0 < H_DIM; c0 += 128) {
        float a = g_T2[d * H_DIM + c0] + g_bconst[c0];
        for (int j = 0; j < m; j++) a = fmaf(clist[j], g_T4[vlist[j] * H_DIM + c0], a);
        g_add[i * H_DIM + c0] = a;
    }
}

// ---------------- main fused GEMM: out = [x | pe] @ [Wc ; W3] + add ----------------
// BM=128, BN=128, BK=16, 256 threads, 8x8 per thread (split 4+4 / 4+4)
__global__ void __launch_bounds__(256) k_gemm(const float* __restrict__ x,
                                              const float* __restrict__ Wout,
                                              float* __restrict__ out) {
    __shared__ float As[16][128];
    __shared__ float Bs[16][128];
    int bm = blockIdx.x, bn = blockIdx.y;
    int tid = threadIdx.x;
    int tm0 = (tid >> 4) * 4;   // 0..60
    int tn0 = (tid & 15) * 4;   // 0..60

    float acc[8][8];
    #pragma unroll
    for (int a = 0; a < 8; a++)
        #pragma unroll
        for (int b = 0; b < 8; b++) acc[a][b] = 0.f;

    int arow = tid >> 1;            // 0..127
    int acol = (tid & 1) * 8;       // 0 / 8
    int brow = tid >> 4;            // 0..15
    int bcol = (tid & 15) * 8;      // 0..120

    const float* W3 = Wout + 1024 * H_DIM;
    int gArow = bm * 128 + arow;
    const float* xrow  = x + gArow * F_DIM;
    const float* perow = g_pe + gArow * H_DIM;

    for (int k0 = 0; k0 < F_DIM + H_DIM; k0 += 16) {
        const float* ap = (k0 < F_DIM) ? (xrow + k0 + acol)
                                       : (perow + (k0 - F_DIM) + acol);
        float4 a0 = *(const float4*)ap;
        float4 a1 = *(const float4*)(ap + 4);
        const float* bp = (k0 < F_DIM)
            ? (g_Wc + (k0 + brow) * H_DIM + bn * 128 + bcol)
            : (W3 + (k0 - F_DIM + brow) * H_DIM + bn * 128 + bcol);
        float4 b0 = *(const float4*)bp;
        float4 b1 = *(const float4*)(bp + 4);

        __syncthreads();  // previous tile's compute done before overwrite
        As[acol + 0][arow] = a0.x; As[acol + 1][arow] = a0.y;
        As[acol + 2][arow] = a0.z; As[acol + 3][arow] = a0.w;
        As[acol + 4][arow] = a1.x; As[acol + 5][arow] = a1.y;
        As[acol + 6][arow] = a1.z; As[acol + 7][arow] = a1.w;
        *(float4*)&Bs[brow][bcol]     = b0;
        *(float4*)&Bs[brow][bcol + 4] = b1;
        __syncthreads();

        #pragma unroll
        for (int kk = 0; kk < 16; kk++) {
            float ar[8], br[8];
            *(float4*)(ar)     = *(const float4*)&As[kk][tm0];
            *(float4*)(ar + 4) = *(const float4*)&As[kk][tm0 + 64];
            *(float4*)(br)     = *(const float4*)&Bs[kk][tn0];
            *(float4*)(br + 4) = *(const float4*)&Bs[kk][tn0 + 64];
            #pragma unroll
            for (int a = 0; a < 8; a++)
                #pragma unroll
                for (int b = 0; b < 8; b++)
                    acc[a][b] = fmaf(ar[a], br[b], acc[a][b]);
        }
    }

    #pragma unroll
    for (int a = 0; a < 8; a++) {
        int r = bm * 128 + ((a < 4) ? (tm0 + a) : (64 + tm0 + a - 4));
        const float* addp = g_add + r * H_DIM + bn * 128;
        float*       op   = out   + r * H_DIM + bn * 128;
        float4 d0 = *(const float4*)(addp + tn0);
        float4 d1 = *(const float4*)(addp + tn0 + 64);
        float4 o0 = make_float4(acc[a][0] + d0.x, acc[a][1] + d0.y,
                                acc[a][2] + d0.z, acc[a][3] + d0.w);
        float4 o1 = make_float4(acc[a][4] + d1.x, acc[a][5] + d1.y,
                                acc[a][6] + d1.z, acc[a][7] + d1.w);
        *(float4*)(op + tn0)      = o0;
        *(float4*)(op + tn0 + 64) = o1;
    }
}

// ---------------- launch ----------------
extern "C" void kernel_launch(void* const* d_in, const int* in_sizes, int n_in,
                              void* d_out, int out_size) {
    const float* x    = (const float*)d_in[0];
    const float* Wf   = (const float*)d_in[1];
    const float* bf   = (const float*)d_in[2];
    const float* Wout = (const float*)d_in[3];
    const float* bo   = (const float*)d_in[4];
    const int*   ei   = (const int*)d_in[5];
    int E = in_sizes[5] / 2;
    float* out = (float*)d_out;

    k_invdiv<<<1, 256>>>();
    k_init<<<(N_NODES + 255) / 256, 256>>>();
    k_edges<<<(E + 255) / 256, 256>>>(ei, E);
    k_wc<<<33, 512>>>(Wf, Wout, bf, bo);
    k_tables<<<74, 512>>>(Wout);
    k_pe<<<N_NODES, 256>>>();
    k_bfs<<<NGRAPH, NPG>>>();
    k_add<<<N_NODES, 128>>>();
    dim3 grid(N_NODES / 128, H_DIM / 128);
    k_gemm<<<grid, 256>>>(x, Wout, out);
}

// round 3
// speedup vs baseline: 1.8505x; 1.8505x over previous
#include <cuda_runtime.h>
#include <cuda_bf16.h>
#include <math.h>
#include <stdint.h>

#define N_NODES 16384
#define F_DIM   256
#define H_DIM   512
#define K_TOT   768          // 256 (x) + 512 (pe)
#define NPG     64
#define NGRAPH  256
#define MAXDEG  512

// ---------------- static device scratch ----------------
__device__ __align__(16) __nv_bfloat16 g_A_hi[N_NODES * K_TOT];
__device__ __align__(16) __nv_bfloat16 g_A_lo[N_NODES * K_TOT];
__device__ __align__(16) __nv_bfloat16 g_BT_hi[H_DIM * K_TOT];   // [n][k]
__device__ __align__(16) __nv_bfloat16 g_BT_lo[H_DIM * K_TOT];
__device__ float g_T2[(MAXDEG + 1) * H_DIM];
__device__ float g_T4[(NPG + 1) * H_DIM];
__device__ float g_bconst[H_DIM];
__device__ __align__(16) float g_add[N_NODES * H_DIM];
__device__ unsigned long long g_adj[N_NODES];
__device__ int g_deg[N_NODES];
__device__ unsigned char g_hist[N_NODES * (NPG + 1)];
__device__ float g_invhi[H_DIM / 2];
__device__ float g_invlo[H_DIM / 2];
__device__ float g_scg[NGRAPH * H_DIM];   // sin/cos(64g * inv_k) pairs
__device__ float g_scr[NPG * H_DIM];      // sin/cos(r * inv_k) pairs

// ---------------- helpers ----------------
__device__ __forceinline__ uint32_t smem_u32(const void* p) {
    uint32_t a;
    asm("{ .reg .u64 t; cvta.to.shared.u64 t, %1; cvt.u32.u64 %0, t; }" : "=r"(a) : "l"(p));
    return a;
}
__device__ __forceinline__ void cpasync16(uint32_t dst, const void* src) {
    asm volatile("cp.async.cg.shared.global [%0], [%1], 16;" :: "r"(dst), "l"(src) : "memory");
}
#define CP_COMMIT() asm volatile("cp.async.commit_group;" ::: "memory")
#define CP_WAIT1()  asm volatile("cp.async.wait_group 1;" ::: "memory")

#define LDSM4(r, addr) \
    asm volatile("ldmatrix.sync.aligned.m8n8.x4.shared.b16 {%0,%1,%2,%3}, [%4];" \
        : "=r"((r)[0]), "=r"((r)[1]), "=r"((r)[2]), "=r"((r)[3]) : "r"(addr))

#define MMA16816(d, a, b) \
    asm volatile("mma.sync.aligned.m16n8k16.row.col.f32.bf16.bf16.f32 " \
        "{%0,%1,%2,%3}, {%4,%5,%6,%7}, {%8,%9}, {%0,%1,%2,%3};" \
        : "+f"((d)[0]), "+f"((d)[1]), "+f"((d)[2]), "+f"((d)[3]) \
        : "r"((a)[0]), "r"((a)[1]), "r"((a)[2]), "r"((a)[3]), "r"((b)[0]), "r"((b)[1]))

__device__ __forceinline__ void bsplit(float v, __nv_bfloat16& h, __nv_bfloat16& l) {
    h = __float2bfloat16(v);
    l = __float2bfloat16(v - __bfloat162float(h));
}

// ---------------- accurate PE angle ----------------
__global__ void k_invdiv() {
    int k = threadIdx.x;
    if (k < H_DIM / 2) {
        double v = exp(-(double)k * (9.210340371976184 / 256.0));
        float hi = (float)v;
        g_invhi[k] = hi;
        g_invlo[k] = (float)(v - (double)hi);
    }
}

__device__ __forceinline__ void pe_sincos(float pos, int k, float* s, float* c) {
    float hi = g_invhi[k], lo = g_invlo[k];
    float p  = pos * hi;
    float e  = fmaf(pos, hi, -p);
    float al = fmaf(pos, lo, e);
    const float I2PI = 0.15915494309189535f;
    const float P2H  = 6.28318548202514648f;
    const float P2L  = -1.7484855e-7f;
    float q = rintf(p * I2PI);
    float r = fmaf(-q, P2H, p);
    r = fmaf(-q, P2L, r);
    r += al;
    sincosf(r, s, c);
}

// ---------------- graph build ----------------
__global__ void k_init() {
    int i = blockIdx.x * blockDim.x + threadIdx.x;
    if (i < N_NODES) { g_deg[i] = 0; g_adj[i] = 0ull; }
}

__global__ void k_edges(const int* __restrict__ ei, int E) {
    int e = blockIdx.x * blockDim.x + threadIdx.x;
    if (e >= E) return;
    int u = ei[e], v = ei[E + e];
    atomicAdd(&g_deg[u], 1);
    atomicAdd(&g_deg[v], 1);
    atomicOr(&g_adj[u], 1ull << (v & 63));
    atomicOr(&g_adj[v], 1ull << (u & 63));
}

// ---------------- small sincos tables for the angle-addition identity ----------------
__global__ void k_sc() {
    int b = blockIdx.x, t = threadIdx.x;
    float s, c;
    if (b < NGRAPH) {
        pe_sincos((float)(64 * b), t, &s, &c);
        g_scg[b * H_DIM + 2 * t] = s; g_scg[b * H_DIM + 2 * t + 1] = c;
    } else {
        int r = b - NGRAPH;
        pe_sincos((float)r, t, &s, &c);
        g_scr[r * H_DIM + 2 * t] = s; g_scr[r * H_DIM + 2 * t + 1] = c;
    }
}

// ---------------- A planes: [x | PE(node idx)] -> bf16 hi/lo ----------------
__global__ void k_aplanes(const float* __restrict__ x) {
    int i = blockIdx.x, t = threadIdx.x;
    int g = i >> 6, r = i & 63;
    float v = x[i * F_DIM + t];
    __nv_bfloat16 h, l;
    bsplit(v, h, l);
    g_A_hi[(size_t)i * K_TOT + t] = h;
    g_A_lo[(size_t)i * K_TOT + t] = l;
    float2 sg = ((const float2*)g_scg)[g * 256 + t];
    float2 sr = ((const float2*)g_scr)[r * 256 + t];
    float s = sg.x * sr.y + sg.y * sr.x;
    float c = sg.y * sr.y - sg.x * sr.x;
    __nv_bfloat16 sh, sl, ch, cl;
    bsplit(s, sh, sl); bsplit(c, ch, cl);
    size_t base = (size_t)i * K_TOT + F_DIM + 2 * t;
    g_A_hi[base] = sh; g_A_hi[base + 1] = ch;
    g_A_lo[base] = sl; g_A_lo[base + 1] = cl;
}

// ---------------- fold: Wc^T (bf16 planes), T2, T4, bconst ----------------
__global__ void k_fold(const float* __restrict__ Wf, const float* __restrict__ Wout,
                       const float* __restrict__ bf, const float* __restrict__ bo) {
    __shared__ float a_sh[2][H_DIM];
    int t = threadIdx.x, b = blockIdx.x;
    int kind, row0;
    const float* B;
    if (b < 128)       { kind = 0; row0 = b * 2;          B = Wout; }
    else if (b < 385)  { kind = 1; row0 = (b - 128) * 2;  B = Wout + 512 * H_DIM; }
    else if (b < 418)  { kind = 2; row0 = (b - 385) * 2;  B = Wout + 1536 * H_DIM; }
    else               { kind = 3; row0 = 0;              B = Wout; }

    if (kind == 0) {
        a_sh[0][t] = Wf[row0 * H_DIM + t];       a_sh[0][t + 256] = Wf[row0 * H_DIM + t + 256];
        a_sh[1][t] = Wf[(row0 + 1) * H_DIM + t]; a_sh[1][t + 256] = Wf[(row0 + 1) * H_DIM + t + 256];
    } else if (kind == 3) {
        a_sh[0][t] = bf[t]; a_sh[0][t + 256] = bf[t + 256];
        a_sh[1][t] = 0.f;   a_sh[1][t + 256] = 0.f;
    } else {
        #pragma unroll
        for (int rr = 0; rr < 2; rr++) {
            float s, c;
            pe_sincos((float)(row0 + rr), t, &s, &c);
            a_sh[rr][2 * t] = s; a_sh[rr][2 * t + 1] = c;
        }
    }
    __syncthreads();

    float acc00 = 0.f, acc01 = 0.f, acc10 = 0.f, acc11 = 0.f;
    const float2* Bp = ((const float2*)B) + t;
    #pragma unroll 4
    for (int h = 0; h < H_DIM; h++) {
        float2 w = Bp[(size_t)h * 256];
        float a0 = a_sh[0][h], a1 = a_sh[1][h];
        acc00 = fmaf(a0, w.x, acc00); acc01 = fmaf(a0, w.y, acc01);
        acc10 = fmaf(a1, w.x, acc10); acc11 = fmaf(a1, w.y, acc11);
    }

    int c0 = 2 * t;
    if (kind == 0) {
        __nv_bfloat16 h, l;
        bsplit(acc00, h, l); g_BT_hi[c0 * K_TOT + row0] = h;           g_BT_lo[c0 * K_TOT + row0] = l;
        bsplit(acc01, h, l); g_BT_hi[(c0 + 1) * K_TOT + row0] = h;     g_BT_lo[(c0 + 1) * K_TOT + row0] = l;
        bsplit(acc10, h, l); g_BT_hi[c0 * K_TOT + row0 + 1] = h;       g_BT_lo[c0 * K_TOT + row0 + 1] = l;
        bsplit(acc11, h, l); g_BT_hi[(c0 + 1) * K_TOT + row0 + 1] = h; g_BT_lo[(c0 + 1) * K_TOT + row0 + 1] = l;
    } else if (kind == 1) {
        if (row0 <= MAXDEG)     { g_T2[row0 * H_DIM + c0] = acc00; g_T2[row0 * H_DIM + c0 + 1] = acc01; }
        if (row0 + 1 <= MAXDEG) { g_T2[(row0 + 1) * H_DIM + c0] = acc10; g_T2[(row0 + 1) * H_DIM + c0 + 1] = acc11; }
    } else if (kind == 2) {
        if (row0 <= NPG)     { g_T4[row0 * H_DIM + c0] = acc00; g_T4[row0 * H_DIM + c0 + 1] = acc01; }
        if (row0 + 1 <= NPG) { g_T4[(row0 + 1) * H_DIM + c0] = acc10; g_T4[(row0 + 1) * H_DIM + c0 + 1] = acc11; }
    } else {
        g_bconst[c0] = acc00 + bo[c0];
        g_bconst[c0 + 1] = acc01 + bo[c0 + 1];
    }
}

// ---------------- W3 transpose + bf16 split into BT cols 256..767 ----------------
__global__ void k_w3t(const float* __restrict__ Wout) {
    __shared__ float sm[64][65];
    int bx = blockIdx.x, by = blockIdx.y;
    int t = threadIdx.x;
    int lr = t >> 6, lc = t & 63;
    #pragma unroll 4
    for (int j = 0; j < 16; j++) {
        int r = lr * 16 + j;
        sm[r][lc] = Wout[(size_t)(1024 + by * 64 + r) * H_DIM + bx * 64 + lc];
    }
    __syncthreads();
    #pragma unroll 4
    for (int j = 0; j < 16; j++) {
        int nl = lr * 16 + j;
        float v = sm[lc][nl];
        __nv_bfloat16 h, l;
        bsplit(v, h, l);
        int n = bx * 64 + nl;
        int k = F_DIM + by * 64 + lc;
        g_BT_hi[(size_t)n * K_TOT + k] = h;
        g_BT_lo[(size_t)n * K_TOT + k] = l;
    }
}

// ---------------- bit-parallel BFS ----------------
__global__ void k_bfs() {
    __shared__ unsigned long long adj_sh[NPG];
    int g = blockIdx.x, s = threadIdx.x;
    adj_sh[s] = g_adj[g * NPG + s];
    __syncthreads();
    unsigned long long reach = 1ull << s;
    unsigned long long frontier = reach;
    unsigned char cnt[NPG + 1];
    #pragma unroll
    for (int v = 0; v <= NPG; v++) cnt[v] = 0;
    cnt[0] = 1;
    int maxfin = 0;
    for (int k = 1; k < NPG; k++) {
        unsigned long long nr = 0, f = frontier;
        while (f) {
            int j = __ffsll((long long)f) - 1;
            f &= f - 1;
            nr |= adj_sh[j];
        }
        unsigned long long nxt = nr & ~reach;
        if (!nxt) break;
        cnt[k] = (unsigned char)__popcll(nxt);
        maxfin = k;
        reach |= nxt;
        frontier = nxt;
    }
    int rem = NPG - __popcll(reach);
    cnt[maxfin + 1] = (unsigned char)(cnt[maxfin + 1] + rem);
    unsigned char* h = g_hist + (size_t)(g * NPG + s) * (NPG + 1);
    #pragma unroll
    for (int v = 0; v <= NPG; v++) h[v] = cnt[v];
}

// ---------------- per-node additive vector ----------------
__global__ void k_add() {
    __shared__ int   vlist[NPG + 1];
    __shared__ float clist[NPG + 1];
    __shared__ int   nnz, sdeg;
    int i = blockIdx.x, tid = threadIdx.x;
    if (tid == 0) {
        const unsigned char* h = g_hist + (size_t)i * (NPG + 1);
        int m = 0;
        for (int v = 0; v <= NPG; v++) {
            int c = h[v];
            if (c) { vlist[m] = v; clist[m] = (float)c * (1.0f / 64.0f); m++; }
        }
        nnz = m;
        int d = g_deg[i];
        sdeg = d > MAXDEG ? MAXDEG : d;
    }
    __syncthreads();
    int d = sdeg, m = nnz;
    for (int c0 = tid; c0 < H_DIM; c0 += 128) {
        float a = g_T2[d * H_DIM + c0] + g_bconst[c0];
        for (int j = 0; j < m; j++) a = fmaf(clist[j], g_T4[vlist[j] * H_DIM + c0], a);
        g_add[(size_t)i * H_DIM + c0] = a;
    }
}

// ---------------- HMMA main GEMM: D = A @ B^T (3-product bf16 split), out = D + add ----------------
// CTA tile 128x128, K-chunk 32, 8 warps (2 m x 4 n), warp tile 64x32.
// smem tiles: 128 rows x 80B stride (64B data) per plane; 4 planes; double buffered.
#define ROWB        80
#define PLANE_STR   (128 * ROWB)         // 10240
#define BUF_STR     (4 * PLANE_STR)      // 40960
#define GEMM_SMEM   (2 * BUF_STR)        // 81920
#define NCHUNK      24

__global__ void __launch_bounds__(256, 2) k_gemm(float* __restrict__ out) {
    extern __shared__ char dsm[];
    uint32_t smem = smem_u32(dsm);

    int tid  = threadIdx.x;
    int lane = tid & 31;
    int wid  = tid >> 5;
    int wm   = wid & 1;          // 0..1  (64 rows each)
    int wn   = wid >> 1;         // 0..3  (32 cols each)
    int bn = blockIdx.x, bm = blockIdx.y;

    // ---- cp.async source pointers (per-thread: row = tid>>1, 32B half = tid&1) ----
    int lrow  = tid >> 1;
    int lhalf = tid & 1;
    const char* srcA_hi = (const char*)(g_A_hi  + (size_t)(bm * 128 + lrow) * K_TOT) + lhalf * 32;
    const char* srcA_lo = (const char*)(g_A_lo  + (size_t)(bm * 128 + lrow) * K_TOT) + lhalf * 32;
    const char* srcB_hi = (const char*)(g_BT_hi + (size_t)(bn * 128 + lrow) * K_TOT) + lhalf * 32;
    const char* srcB_lo = (const char*)(g_BT_lo + (size_t)(bn * 128 + lrow) * K_TOT) + lhalf * 32;
    uint32_t sdst = smem + (uint32_t)lrow * ROWB + (uint32_t)lhalf * 32;

    // ---- ldmatrix lane address offsets ----
    int q  = lane >> 3, rl = lane & 7;
    uint32_t aoff = (uint32_t)((wm * 64 + 8 * (q & 1) + rl) * ROWB + (8 * (q >> 1)) * 2);
    uint32_t boff = (uint32_t)((wn * 32 + 8 * (q >> 1) + rl) * ROWB + (8 * (q & 1)) * 2);

    float acc[4][4][4];
    #pragma unroll
    for (int a = 0; a < 4; a++)
        #pragma unroll
        for (int b = 0; b < 4; b++)
            #pragma unroll
            for (int e = 0; e < 4; e++) acc[a][b][e] = 0.f;

    // ---- prologue: load chunk 0 into buffer 0 ----
    {
        uint32_t d = sdst;
        cpasync16(d + 0 * PLANE_STR, srcA_hi);      cpasync16(d + 0 * PLANE_STR + 16, srcA_hi + 16);
        cpasync16(d + 1 * PLANE_STR, srcA_lo);      cpasync16(d + 1 * PLANE_STR + 16, srcA_lo + 16);
        cpasync16(d + 2 * PLANE_STR, srcB_hi);      cpasync16(d + 2 * PLANE_STR + 16, srcB_hi + 16);
        cpasync16(d + 3 * PLANE_STR, srcB_lo);      cpasync16(d + 3 * PLANE_STR + 16, srcB_lo + 16);
        CP_COMMIT();
    }

    for (int c = 0; c < NCHUNK; c++) {
        int buf = c & 1;
        if (c + 1 < NCHUNK) {
            uint32_t d = sdst + (uint32_t)(buf ^ 1) * BUF_STR;
            const char* oA_hi = srcA_hi + (c + 1) * 64;
            const char* oA_lo = srcA_lo + (c + 1) * 64;
            const char* oB_hi = srcB_hi + (c + 1) * 64;
            const char* oB_lo = srcB_lo + (c + 1) * 64;
            cpasync16(d + 0 * PLANE_STR, oA_hi);    cpasync16(d + 0 * PLANE_STR + 16, oA_hi + 16);
            cpasync16(d + 1 * PLANE_STR, oA_lo);    cpasync16(d + 1 * PLANE_STR + 16, oA_lo + 16);
            cpasync16(d + 2 * PLANE_STR, oB_hi);    cpasync16(d + 2 * PLANE_STR + 16, oB_hi + 16);
            cpasync16(d + 3 * PLANE_STR, oB_lo);    cpasync16(d + 3 * PLANE_STR + 16, oB_lo + 16);
        }
        CP_COMMIT();
        CP_WAIT1();
        __syncthreads();

        uint32_t sA = smem + (uint32_t)buf * BUF_STR;
        uint32_t sB = sA + 2 * PLANE_STR;

        #pragma unroll
        for (int kk = 0; kk < 2; kk++) {
            uint32_t ah[4][4], al[4][4];
            #pragma unroll
            for (int mf = 0; mf < 4; mf++) {
                uint32_t ad = sA + aoff + (uint32_t)mf * (16 * ROWB) + (uint32_t)kk * 32;
                LDSM4(ah[mf], ad);
                LDSM4(al[mf], ad + PLANE_STR);
            }
            uint32_t bh[2][4], bl[2][4];
            #pragma unroll
            for (int nf2 = 0; nf2 < 2; nf2++) {
                uint32_t bd = sB + boff + (uint32_t)nf2 * (16 * ROWB) + (uint32_t)kk * 32;
                LDSM4(bh[nf2], bd);
                LDSM4(bl[nf2], bd + PLANE_STR);
            }
            #pragma unroll
            for (int mf = 0; mf < 4; mf++) {
                #pragma unroll
                for (int nf = 0; nf < 4; nf++) {
                    int nf2 = nf >> 1, nh = nf & 1;
                    MMA16816(acc[mf][nf], ah[mf], &bh[nf2][nh * 2]);
                    MMA16816(acc[mf][nf], ah[mf], &bl[nf2][nh * 2]);
                    MMA16816(acc[mf][nf], al[mf], &bh[nf2][nh * 2]);
                }
            }
        }
        __syncthreads();
    }

    // ---- epilogue: out = acc + g_add ----
    int r0 = bm * 128 + wm * 64 + (lane >> 2);
    int c0 = bn * 128 + wn * 32 + 2 * (lane & 3);
    #pragma unroll
    for (int mf = 0; mf < 4; mf++) {
        #pragma unroll
        for (int nf = 0; nf < 4; nf++) {
            int r = r0 + mf * 16;
            int c = c0 + nf * 8;
            float2 a0 = *(const float2*)&g_add[(size_t)r * H_DIM + c];
            float2 a1 = *(const float2*)&g_add[(size_t)(r + 8) * H_DIM + c];
            float2 o0 = make_float2(acc[mf][nf][0] + a0.x, acc[mf][nf][1] + a0.y);
            float2 o1 = make_float2(acc[mf][nf][2] + a1.x, acc[mf][nf][3] + a1.y);
            *(float2*)&out[(size_t)r * H_DIM + c]       = o0;
            *(float2*)&out[(size_t)(r + 8) * H_DIM + c] = o1;
        }
    }
}

// ---------------- launch ----------------
extern "C" void kernel_launch(void* const* d_in, const int* in_sizes, int n_in,
                              void* d_out, int out_size) {
    const float* x    = (const float*)d_in[0];
    const float* Wf   = (const float*)d_in[1];
    const float* bf   = (const float*)d_in[2];
    const float* Wout = (const float*)d_in[3];
    const float* bo   = (const float*)d_in[4];
    const int*   ei   = (const int*)d_in[5];
    int E = in_sizes[5] / 2;
    float* out = (float*)d_out;

    cudaFuncSetAttribute(k_gemm, cudaFuncAttributeMaxDynamicSharedMemorySize, GEMM_SMEM);

    k_invdiv<<<1, 256>>>();
    k_init<<<64, 256>>>();
    k_edges<<<(E + 255) / 256, 256>>>(ei, E);
    k_sc<<<NGRAPH + NPG, 256>>>();
    k_aplanes<<<N_NODES, 256>>>(x);
    k_fold<<<419, 256>>>(Wf, Wout, bf, bo);
    k_w3t<<<dim3(8, 8), 256>>>(Wout);
    k_bfs<<<NGRAPH, NPG>>>();
    k_add<<<N_NODES, 128>>>();
    k_gemm<<<dim3(4, 128), 256, GEMM_SMEM>>>(out);
}

// round 4
// speedup vs baseline: 2.1521x; 1.1630x over previous
#include <cuda_runtime.h>
#include <cuda_fp16.h>
#include <math.h>
#include <stdint.h>

#define N_NODES 16384
#define F_DIM   256
#define H_DIM   512
#define K_TOT   768          // 256 (x) + 512 (pe)
#define NPG     64
#define NGRAPH  256
#define MAXDEG  512

// ---------------- static device scratch ----------------
__device__ __align__(16) __half g_A_hi[N_NODES * K_TOT];
__device__ __align__(16) __half g_A_lo[N_NODES * K_TOT];
__device__ __align__(16) __half g_B[H_DIM * K_TOT];     // B^T: [n][k], single fp16
__device__ float g_T2[(MAXDEG + 1) * H_DIM];
__device__ float g_T4[(NPG + 1) * H_DIM];
__device__ float g_bconst[H_DIM];
__device__ __align__(16) float g_add[N_NODES * H_DIM];
__device__ unsigned long long g_adj[N_NODES];
__device__ int g_deg[N_NODES];
__device__ unsigned char g_hist[N_NODES * (NPG + 1)];
__device__ float g_invhi[H_DIM / 2];
__device__ float g_invlo[H_DIM / 2];
__device__ float g_scg[NGRAPH * H_DIM];   // sin/cos(64g * inv_k) pairs
__device__ float g_scr[NPG * H_DIM];      // sin/cos(r * inv_k) pairs

// ---------------- helpers ----------------
__device__ __forceinline__ uint32_t smem_u32(const void* p) {
    uint32_t a;
    asm("{ .reg .u64 t; cvta.to.shared.u64 t, %1; cvt.u32.u64 %0, t; }" : "=r"(a) : "l"(p));
    return a;
}
__device__ __forceinline__ void cpasync16(uint32_t dst, const void* src) {
    asm volatile("cp.async.cg.shared.global [%0], [%1], 16;" :: "r"(dst), "l"(src) : "memory");
}
#define CP_COMMIT() asm volatile("cp.async.commit_group;" ::: "memory")
#define CP_WAIT1()  asm volatile("cp.async.wait_group 1;" ::: "memory")

#define LDSM4(r, addr) \
    asm volatile("ldmatrix.sync.aligned.m8n8.x4.shared.b16 {%0,%1,%2,%3}, [%4];" \
        : "=r"((r)[0]), "=r"((r)[1]), "=r"((r)[2]), "=r"((r)[3]) : "r"(addr))

#define MMA16816(d, a, b) \
    asm volatile("mma.sync.aligned.m16n8k16.row.col.f32.f16.f16.f32 " \
        "{%0,%1,%2,%3}, {%4,%5,%6,%7}, {%8,%9}, {%0,%1,%2,%3};" \
        : "+f"((d)[0]), "+f"((d)[1]), "+f"((d)[2]), "+f"((d)[3]) \
        : "r"((a)[0]), "r"((a)[1]), "r"((a)[2]), "r"((a)[3]), "r"((b)[0]), "r"((b)[1]))

__device__ __forceinline__ void fsplit(float v, __half& h, __half& l) {
    h = __float2half(v);
    l = __float2half(v - __half2float(h));
}

// ---------------- accurate PE angle ----------------
__device__ __forceinline__ void pe_sincos(float pos, int k, float* s, float* c) {
    float hi = g_invhi[k], lo = g_invlo[k];
    float p  = pos * hi;
    float e  = fmaf(pos, hi, -p);
    float al = fmaf(pos, lo, e);
    const float I2PI = 0.15915494309189535f;
    const float P2H  = 6.28318548202514648f;
    const float P2L  = -1.7484855e-7f;
    float q = rintf(p * I2PI);
    float r = fmaf(-q, P2H, p);
    r = fmaf(-q, P2L, r);
    r += al;
    sincosf(r, s, c);
}

// ---------------- init (deg/adj clear + invdiv table) ----------------
__global__ void k_init() {
    int i = blockIdx.x * blockDim.x + threadIdx.x;
    if (i < N_NODES) { g_deg[i] = 0; g_adj[i] = 0ull; }
    if (i < H_DIM / 2) {
        double v = exp(-(double)i * (9.210340371976184 / 256.0));
        float hi = (float)v;
        g_invhi[i] = hi;
        g_invlo[i] = (float)(v - (double)hi);
    }
}

__global__ void k_edges(const int* __restrict__ ei, int E) {
    int e = blockIdx.x * blockDim.x + threadIdx.x;
    if (e >= E) return;
    int u = ei[e], v = ei[E + e];
    atomicAdd(&g_deg[u], 1);
    atomicAdd(&g_deg[v], 1);
    atomicOr(&g_adj[u], 1ull << (v & 63));
    atomicOr(&g_adj[v], 1ull << (u & 63));
}

// ---------------- small sincos tables for the angle-addition identity ----------------
__global__ void k_sc() {
    int b = blockIdx.x, t = threadIdx.x;
    float s, c;
    if (b < NGRAPH) {
        pe_sincos((float)(64 * b), t, &s, &c);
        g_scg[b * H_DIM + 2 * t] = s; g_scg[b * H_DIM + 2 * t + 1] = c;
    } else {
        int r = b - NGRAPH;
        pe_sincos((float)r, t, &s, &c);
        g_scr[r * H_DIM + 2 * t] = s; g_scr[r * H_DIM + 2 * t + 1] = c;
    }
}

// ---------------- A planes: [x | PE(node idx)] -> fp16 hi/lo ----------------
__global__ void k_aplanes(const float* __restrict__ x) {
    int i = blockIdx.x, t = threadIdx.x;
    int g = i >> 6, r = i & 63;
    float v = x[i * F_DIM + t];
    __half h, l;
    fsplit(v, h, l);
    g_A_hi[(size_t)i * K_TOT + t] = h;
    g_A_lo[(size_t)i * K_TOT + t] = l;
    float2 sg = ((const float2*)g_scg)[g * 256 + t];
    float2 sr = ((const float2*)g_scr)[r * 256 + t];
    float s = sg.x * sr.y + sg.y * sr.x;
    float c = sg.y * sr.y - sg.x * sr.x;
    __half sh, sl, ch, cl;
    fsplit(s, sh, sl); fsplit(c, ch, cl);
    size_t base = (size_t)i * K_TOT + F_DIM + 2 * t;
    g_A_hi[base] = sh; g_A_hi[base + 1] = ch;
    g_A_lo[base] = sl; g_A_lo[base + 1] = cl;
}

// ---------------- fold: Wc^T (fp16), T2, T4, bconst ----------------
__global__ void k_fold(const float* __restrict__ Wf, const float* __restrict__ Wout,
                       const float* __restrict__ bf, const float* __restrict__ bo) {
    __shared__ float a_sh[2][H_DIM];
    int t = threadIdx.x, b = blockIdx.x;
    int kind, row0;
    const float* B;
    if (b < 128)       { kind = 0; row0 = b * 2;          B = Wout; }
    else if (b < 385)  { kind = 1; row0 = (b - 128) * 2;  B = Wout + 512 * H_DIM; }
    else if (b < 418)  { kind = 2; row0 = (b - 385) * 2;  B = Wout + 1536 * H_DIM; }
    else               { kind = 3; row0 = 0;              B = Wout; }

    if (kind == 0) {
        a_sh[0][t] = Wf[row0 * H_DIM + t];       a_sh[0][t + 256] = Wf[row0 * H_DIM + t + 256];
        a_sh[1][t] = Wf[(row0 + 1) * H_DIM + t]; a_sh[1][t + 256] = Wf[(row0 + 1) * H_DIM + t + 256];
    } else if (kind == 3) {
        a_sh[0][t] = bf[t]; a_sh[0][t + 256] = bf[t + 256];
        a_sh[1][t] = 0.f;   a_sh[1][t + 256] = 0.f;
    } else {
        #pragma unroll
        for (int rr = 0; rr < 2; rr++) {
            float s, c;
            pe_sincos((float)(row0 + rr), t, &s, &c);
            a_sh[rr][2 * t] = s; a_sh[rr][2 * t + 1] = c;
        }
    }
    __syncthreads();

    float acc00 = 0.f, acc01 = 0.f, acc10 = 0.f, acc11 = 0.f;
    const float2* Bp = ((const float2*)B) + t;
    #pragma unroll 4
    for (int h = 0; h < H_DIM; h++) {
        float2 w = Bp[(size_t)h * 256];
        float a0 = a_sh[0][h], a1 = a_sh[1][h];
        acc00 = fmaf(a0, w.x, acc00); acc01 = fmaf(a0, w.y, acc01);
        acc10 = fmaf(a1, w.x, acc10); acc11 = fmaf(a1, w.y, acc11);
    }

    int c0 = 2 * t;
    if (kind == 0) {
        g_B[c0 * K_TOT + row0]           = __float2half(acc00);
        g_B[(c0 + 1) * K_TOT + row0]     = __float2half(acc01);
        g_B[c0 * K_TOT + row0 + 1]       = __float2half(acc10);
        g_B[(c0 + 1) * K_TOT + row0 + 1] = __float2half(acc11);
    } else if (kind == 1) {
        if (row0 <= MAXDEG)     { g_T2[row0 * H_DIM + c0] = acc00; g_T2[row0 * H_DIM + c0 + 1] = acc01; }
        if (row0 + 1 <= MAXDEG) { g_T2[(row0 + 1) * H_DIM + c0] = acc10; g_T2[(row0 + 1) * H_DIM + c0 + 1] = acc11; }
    } else if (kind == 2) {
        if (row0 <= NPG)     { g_T4[row0 * H_DIM + c0] = acc00; g_T4[row0 * H_DIM + c0 + 1] = acc01; }
        if (row0 + 1 <= NPG) { g_T4[(row0 + 1) * H_DIM + c0] = acc10; g_T4[(row0 + 1) * H_DIM + c0 + 1] = acc11; }
    } else {
        g_bconst[c0] = acc00 + bo[c0];
        g_bconst[c0 + 1] = acc01 + bo[c0 + 1];
    }
}

// ---------------- W3 transpose + fp16 into B cols 256..767 ----------------
__global__ void k_w3t(const float* __restrict__ Wout) {
    __shared__ float sm[64][65];
    int bx = blockIdx.x, by = blockIdx.y;
    int t = threadIdx.x;
    int lr = t >> 6, lc = t & 63;
    #pragma unroll 4
    for (int j = 0; j < 16; j++) {
        int r = lr * 16 + j;
        sm[r][lc] = Wout[(size_t)(1024 + by * 64 + r) * H_DIM + bx * 64 + lc];
    }
    __syncthreads();
    #pragma unroll 4
    for (int j = 0; j < 16; j++) {
        int nl = lr * 16 + j;
        float v = sm[lc][nl];
        int n = bx * 64 + nl;
        int k = F_DIM + by * 64 + lc;
        g_B[(size_t)n * K_TOT + k] = __float2half(v);
    }
}

// ---------------- bit-parallel BFS ----------------
__global__ void k_bfs() {
    __shared__ unsigned long long adj_sh[NPG];
    int g = blockIdx.x, s = threadIdx.x;
    adj_sh[s] = g_adj[g * NPG + s];
    __syncthreads();
    unsigned long long reach = 1ull << s;
    unsigned long long frontier = reach;
    unsigned char cnt[NPG + 1];
    #pragma unroll
    for (int v = 0; v <= NPG; v++) cnt[v] = 0;
    cnt[0] = 1;
    int maxfin = 0;
    for (int k = 1; k < NPG; k++) {
        unsigned long long nr = 0, f = frontier;
        while (f) {
            int j = __ffsll((long long)f) - 1;
            f &= f - 1;
            nr |= adj_sh[j];
        }
        unsigned long long nxt = nr & ~reach;
        if (!nxt) break;
        cnt[k] = (unsigned char)__popcll(nxt);
        maxfin = k;
        reach |= nxt;
        frontier = nxt;
    }
    int rem = NPG - __popcll(reach);
    cnt[maxfin + 1] = (unsigned char)(cnt[maxfin + 1] + rem);
    unsigned char* h = g_hist + (size_t)(g * NPG + s) * (NPG + 1);
    #pragma unroll
    for (int v = 0; v <= NPG; v++) h[v] = cnt[v];
}

// ---------------- per-node additive vector ----------------
__global__ void k_add() {
    __shared__ int   vlist[NPG + 1];
    __shared__ float clist[NPG + 1];
    __shared__ int   nnz, sdeg;
    int i = blockIdx.x, tid = threadIdx.x;
    if (tid == 0) {
        const unsigned char* h = g_hist + (size_t)i * (NPG + 1);
        int m = 0;
        for (int v = 0; v <= NPG; v++) {
            int c = h[v];
            if (c) { vlist[m] = v; clist[m] = (float)c * (1.0f / 64.0f); m++; }
        }
        nnz = m;
        int d = g_deg[i];
        sdeg = d > MAXDEG ? MAXDEG : d;
    }
    __syncthreads();
    int d = sdeg, m = nnz;
    for (int c0 = tid; c0 < H_DIM; c0 += 128) {
        float a = g_T2[d * H_DIM + c0] + g_bconst[c0];
        for (int j = 0; j < m; j++) a = fmaf(clist[j], g_T4[vlist[j] * H_DIM + c0], a);
        g_add[(size_t)i * H_DIM + c0] = a;
    }
}

// ---------------- HMMA GEMM: D = (Ah+Al) @ B^T (fp16 2-product), out = D + add ----------------
// CTA tile 128x128, K-chunk 32, 8 warps (2m x 4n), warp tile 64x32.
// smem: per stage 3 planes (Ah, Al, B) of 128 rows x 80B stride; 3 stages.
#define ROWB        80
#define PLANE_STR   (128 * ROWB)         // 10240
#define STAGE_STR   (3 * PLANE_STR)      // 30720
#define NSTAGE      3
#define GEMM_SMEM   (NSTAGE * STAGE_STR) // 92160
#define NCHUNK      24

__global__ void __launch_bounds__(256, 2) k_gemm(float* __restrict__ out) {
    extern __shared__ char dsm[];
    uint32_t smem = smem_u32(dsm);

    int tid  = threadIdx.x;
    int lane = tid & 31;
    int wid  = tid >> 5;
    int wm   = wid & 1;
    int wn   = wid >> 1;
    int bn = blockIdx.x, bm = blockIdx.y;

    int lrow  = tid >> 1;
    int lhalf = tid & 1;
    const char* srcAh = (const char*)(g_A_hi + (size_t)(bm * 128 + lrow) * K_TOT) + lhalf * 32;
    const char* srcAl = (const char*)(g_A_lo + (size_t)(bm * 128 + lrow) * K_TOT) + lhalf * 32;
    const char* srcB  = (const char*)(g_B    + (size_t)(bn * 128 + lrow) * K_TOT) + lhalf * 32;
    uint32_t sdst = smem + (uint32_t)lrow * ROWB + (uint32_t)lhalf * 32;

    int q  = lane >> 3, rl = lane & 7;
    uint32_t aoff = (uint32_t)((wm * 64 + 8 * (q & 1) + rl) * ROWB + (8 * (q >> 1)) * 2);
    uint32_t boff = (uint32_t)((wn * 32 + 8 * (q >> 1) + rl) * ROWB + (8 * (q & 1)) * 2);

    float acc[4][4][4];
    #pragma unroll
    for (int a = 0; a < 4; a++)
        #pragma unroll
        for (int b = 0; b < 4; b++)
            #pragma unroll
            for (int e = 0; e < 4; e++) acc[a][b][e] = 0.f;

    // prologue: chunks 0,1 into stages 0,1
    #pragma unroll
    for (int s = 0; s < 2; s++) {
        uint32_t d = sdst + (uint32_t)s * STAGE_STR;
        cpasync16(d + 0 * PLANE_STR, srcAh + s * 64);  cpasync16(d + 0 * PLANE_STR + 16, srcAh + s * 64 + 16);
        cpasync16(d + 1 * PLANE_STR, srcAl + s * 64);  cpasync16(d + 1 * PLANE_STR + 16, srcAl + s * 64 + 16);
        cpasync16(d + 2 * PLANE_STR, srcB  + s * 64);  cpasync16(d + 2 * PLANE_STR + 16, srcB  + s * 64 + 16);
        CP_COMMIT();
    }

    int stage = 0, nstage = 2;
    for (int c = 0; c < NCHUNK; c++) {
        CP_WAIT1();
        __syncthreads();
        if (c + 2 < NCHUNK) {
            uint32_t d = sdst + (uint32_t)nstage * STAGE_STR;
            const char* oAh = srcAh + (c + 2) * 64;
            const char* oAl = srcAl + (c + 2) * 64;
            const char* oB  = srcB  + (c + 2) * 64;
            cpasync16(d + 0 * PLANE_STR, oAh);  cpasync16(d + 0 * PLANE_STR + 16, oAh + 16);
            cpasync16(d + 1 * PLANE_STR, oAl);  cpasync16(d + 1 * PLANE_STR + 16, oAl + 16);
            cpasync16(d + 2 * PLANE_STR, oB);   cpasync16(d + 2 * PLANE_STR + 16, oB + 16);
        }
        CP_COMMIT();

        uint32_t sA  = smem + (uint32_t)stage * STAGE_STR;
        uint32_t sAl = sA + PLANE_STR;
        uint32_t sB  = sA + 2 * PLANE_STR;

        #pragma unroll
        for (int kk = 0; kk < 2; kk++) {
            uint32_t ah[4][4], al[4][4];
            #pragma unroll
            for (int mf = 0; mf < 4; mf++) {
                uint32_t ad = sA + aoff + (uint32_t)mf * (16 * ROWB) + (uint32_t)kk * 32;
                LDSM4(ah[mf], ad);
                LDSM4(al[mf], ad + PLANE_STR);
            }
            uint32_t bh[2][4];
            #pragma unroll
            for (int nf2 = 0; nf2 < 2; nf2++) {
                uint32_t bd = sB + boff + (uint32_t)nf2 * (16 * ROWB) + (uint32_t)kk * 32;
                LDSM4(bh[nf2], bd);
            }
            #pragma unroll
            for (int mf = 0; mf < 4; mf++) {
                #pragma unroll
                for (int nf = 0; nf < 4; nf++) {
                    int nf2 = nf >> 1, nh = nf & 1;
                    MMA16816(acc[mf][nf], ah[mf], &bh[nf2][nh * 2]);
                    MMA16816(acc[mf][nf], al[mf], &bh[nf2][nh * 2]);
                }
            }
        }
        stage = (stage + 1) % NSTAGE;
        nstage = (nstage + 1) % NSTAGE;
        (void)sAl;
    }

    // epilogue: out = acc + g_add
    int r0 = bm * 128 + wm * 64 + (lane >> 2);
    int c0 = bn * 128 + wn * 32 + 2 * (lane & 3);
    #pragma unroll
    for (int mf = 0; mf < 4; mf++) {
        #pragma unroll
        for (int nf = 0; nf < 4; nf++) {
            int r = r0 + mf * 16;
            int c = c0 + nf * 8;
            float2 a0 = *(const float2*)&g_add[(size_t)r * H_DIM + c];
            float2 a1 = *(const float2*)&g_add[(size_t)(r + 8) * H_DIM + c];
            float2 o0 = make_float2(acc[mf][nf][0] + a0.x, acc[mf][nf][1] + a0.y);
            float2 o1 = make_float2(acc[mf][nf][2] + a1.x, acc[mf][nf][3] + a1.y);
            *(float2*)&out[(size_t)r * H_DIM + c]       = o0;
            *(float2*)&out[(size_t)(r + 8) * H_DIM + c] = o1;
        }
    }
}

// ---------------- launch ----------------
extern "C" void kernel_launch(void* const* d_in, const int* in_sizes, int n_in,
                              void* d_out, int out_size) {
    const float* x    = (const float*)d_in[0];
    const float* Wf   = (const float*)d_in[1];
    const float* bf   = (const float*)d_in[2];
    const float* Wout = (const float*)d_in[3];
    const float* bo   = (const float*)d_in[4];
    const int*   ei   = (const int*)d_in[5];
    int E = in_sizes[5] / 2;
    float* out = (float*)d_out;

    cudaFuncSetAttribute(k_gemm, cudaFuncAttributeMaxDynamicSharedMemorySize, GEMM_SMEM);

    k_init<<<64, 256>>>();
    k_edges<<<(E + 255) / 256, 256>>>(ei, E);
    k_sc<<<NGRAPH + NPG, 256>>>();
    k_aplanes<<<N_NODES, 256>>>(x);
    k_fold<<<419, 256>>>(Wf, Wout, bf, bo);
    k_w3t<<<dim3(8, 8), 256>>>(Wout);
    k_bfs<<<NGRAPH, NPG>>>();
    k_add<<<N_NODES, 128>>>();
    k_gemm<<<dim3(4, 128), 256, GEMM_SMEM>>>(out);
}

// round 5
// speedup vs baseline: 2.5167x; 1.1694x over previous
#include <cuda_runtime.h>
#include <cuda_fp16.h>
#include <math.h>
#include <stdint.h>

#define N_NODES 16384
#define F_DIM   256
#define H_DIM   512
#define K_TOT   768          // 256 (x) + 512 (pe)
#define NPG     64
#define NGRAPH  256
#define MAXDEG  512

// ---------------- static device scratch ----------------
__device__ __align__(16) __half g_A[N_NODES * K_TOT];   // [x | PE] fp16
__device__ __align__(16) __half g_B[H_DIM * K_TOT];     // B^T: [n][k] fp16
__device__ float g_T2[(MAXDEG + 1) * H_DIM];
__device__ float g_T4[(NPG + 1) * H_DIM];
__device__ float g_bconst[H_DIM];
__device__ __align__(16) float g_add[N_NODES * H_DIM];
__device__ unsigned long long g_adj[N_NODES];
__device__ int g_deg[N_NODES];
__device__ unsigned char g_hist[N_NODES * (NPG + 1)];
__device__ float g_invhi[H_DIM / 2];
__device__ float g_invlo[H_DIM / 2];
__device__ float g_scg[NGRAPH * H_DIM];   // sin/cos(64g * inv_k) pairs
__device__ float g_scr[NPG * H_DIM];      // sin/cos(r * inv_k) pairs

// ---------------- helpers ----------------
__device__ __forceinline__ uint32_t smem_u32(const void* p) {
    uint32_t a;
    asm("{ .reg .u64 t; cvta.to.shared.u64 t, %1; cvt.u32.u64 %0, t; }" : "=r"(a) : "l"(p));
    return a;
}
__device__ __forceinline__ void cpasync16(uint32_t dst, const void* src) {
    asm volatile("cp.async.cg.shared.global [%0], [%1], 16;" :: "r"(dst), "l"(src) : "memory");
}
#define CP_COMMIT() asm volatile("cp.async.commit_group;" ::: "memory")
#define CP_WAIT2()  asm volatile("cp.async.wait_group 2;" ::: "memory")

#define LDSM4(r, addr) \
    asm volatile("ldmatrix.sync.aligned.m8n8.x4.shared.b16 {%0,%1,%2,%3}, [%4];" \
        : "=r"((r)[0]), "=r"((r)[1]), "=r"((r)[2]), "=r"((r)[3]) : "r"(addr))

#define MMA16816(d, a, b) \
    asm volatile("mma.sync.aligned.m16n8k16.row.col.f32.f16.f16.f32 " \
        "{%0,%1,%2,%3}, {%4,%5,%6,%7}, {%8,%9}, {%0,%1,%2,%3};" \
        : "+f"((d)[0]), "+f"((d)[1]), "+f"((d)[2]), "+f"((d)[3]) \
        : "r"((a)[0]), "r"((a)[1]), "r"((a)[2]), "r"((a)[3]), "r"((b)[0]), "r"((b)[1]))

// ---------------- accurate PE angle ----------------
__device__ __forceinline__ void pe_sincos(float pos, int k, float* s, float* c) {
    float hi = g_invhi[k], lo = g_invlo[k];
    float p  = pos * hi;
    float e  = fmaf(pos, hi, -p);
    float al = fmaf(pos, lo, e);
    const float I2PI = 0.15915494309189535f;
    const float P2H  = 6.28318548202514648f;
    const float P2L  = -1.7484855e-7f;
    float q = rintf(p * I2PI);
    float r = fmaf(-q, P2H, p);
    r = fmaf(-q, P2L, r);
    r += al;
    sincosf(r, s, c);
}

// ---------------- init (deg/adj clear + invdiv table) ----------------
__global__ void k_init() {
    int i = blockIdx.x * blockDim.x + threadIdx.x;
    if (i < N_NODES) { g_deg[i] = 0; g_adj[i] = 0ull; }
    if (i < H_DIM / 2) {
        double v = exp(-(double)i * (9.210340371976184 / 256.0));
        float hi = (float)v;
        g_invhi[i] = hi;
        g_invlo[i] = (float)(v - (double)hi);
    }
}

__global__ void k_edges(const int* __restrict__ ei, int E) {
    int e = blockIdx.x * blockDim.x + threadIdx.x;
    if (e >= E) return;
    int u = ei[e], v = ei[E + e];
    atomicAdd(&g_deg[u], 1);
    atomicAdd(&g_deg[v], 1);
    atomicOr(&g_adj[u], 1ull << (v & 63));
    atomicOr(&g_adj[v], 1ull << (u & 63));
}

// ---------------- small sincos tables for the angle-addition identity ----------------
__global__ void k_sc() {
    int b = blockIdx.x, t = threadIdx.x;
    float s, c;
    if (b < NGRAPH) {
        pe_sincos((float)(64 * b), t, &s, &c);
        g_scg[b * H_DIM + 2 * t] = s; g_scg[b * H_DIM + 2 * t + 1] = c;
    } else {
        int r = b - NGRAPH;
        pe_sincos((float)r, t, &s, &c);
        g_scr[r * H_DIM + 2 * t] = s; g_scr[r * H_DIM + 2 * t + 1] = c;
    }
}

// ---------------- A plane: [x | PE(node idx)] -> fp16 ----------------
__global__ void k_aplanes(const float* __restrict__ x) {
    int i = blockIdx.x, t = threadIdx.x;
    int g = i >> 6, r = i & 63;
    float v = x[i * F_DIM + t];
    g_A[(size_t)i * K_TOT + t] = __float2half(v);
    float2 sg = ((const float2*)g_scg)[g * 256 + t];
    float2 sr = ((const float2*)g_scr)[r * 256 + t];
    float s = sg.x * sr.y + sg.y * sr.x;
    float c = sg.y * sr.y - sg.x * sr.x;
    __half2 sc = __floats2half2_rn(s, c);
    *(__half2*)(g_A + (size_t)i * K_TOT + F_DIM + 2 * t) = sc;
}

// ---------------- fold: Wc^T (fp16), T2, T4, bconst ----------------
__global__ void k_fold(const float* __restrict__ Wf, const float* __restrict__ Wout,
                       const float* __restrict__ bf, const float* __restrict__ bo) {
    __shared__ float a_sh[2][H_DIM];
    int t = threadIdx.x, b = blockIdx.x;
    int kind, row0;
    const float* B;
    if (b < 128)       { kind = 0; row0 = b * 2;          B = Wout; }
    else if (b < 385)  { kind = 1; row0 = (b - 128) * 2;  B = Wout + 512 * H_DIM; }
    else if (b < 418)  { kind = 2; row0 = (b - 385) * 2;  B = Wout + 1536 * H_DIM; }
    else               { kind = 3; row0 = 0;              B = Wout; }

    if (kind == 0) {
        a_sh[0][t] = Wf[row0 * H_DIM + t];       a_sh[0][t + 256] = Wf[row0 * H_DIM + t + 256];
        a_sh[1][t] = Wf[(row0 + 1) * H_DIM + t]; a_sh[1][t + 256] = Wf[(row0 + 1) * H_DIM + t + 256];
    } else if (kind == 3) {
        a_sh[0][t] = bf[t]; a_sh[0][t + 256] = bf[t + 256];
        a_sh[1][t] = 0.f;   a_sh[1][t + 256] = 0.f;
    } else {
        #pragma unroll
        for (int rr = 0; rr < 2; rr++) {
            float s, c;
            pe_sincos((float)(row0 + rr), t, &s, &c);
            a_sh[rr][2 * t] = s; a_sh[rr][2 * t + 1] = c;
        }
    }
    __syncthreads();

    float acc00 = 0.f, acc01 = 0.f, acc10 = 0.f, acc11 = 0.f;
    const float2* Bp = ((const float2*)B) + t;
    #pragma unroll 4
    for (int h = 0; h < H_DIM; h++) {
        float2 w = Bp[(size_t)h * 256];
        float a0 = a_sh[0][h], a1 = a_sh[1][h];
        acc00 = fmaf(a0, w.x, acc00); acc01 = fmaf(a0, w.y, acc01);
        acc10 = fmaf(a1, w.x, acc10); acc11 = fmaf(a1, w.y, acc11);
    }

    int c0 = 2 * t;
    if (kind == 0) {
        g_B[c0 * K_TOT + row0]           = __float2half(acc00);
        g_B[(c0 + 1) * K_TOT + row0]     = __float2half(acc01);
        g_B[c0 * K_TOT + row0 + 1]       = __float2half(acc10);
        g_B[(c0 + 1) * K_TOT + row0 + 1] = __float2half(acc11);
    } else if (kind == 1) {
        if (row0 <= MAXDEG)     { g_T2[row0 * H_DIM + c0] = acc00; g_T2[row0 * H_DIM + c0 + 1] = acc01; }
        if (row0 + 1 <= MAXDEG) { g_T2[(row0 + 1) * H_DIM + c0] = acc10; g_T2[(row0 + 1) * H_DIM + c0 + 1] = acc11; }
    } else if (kind == 2) {
        if (row0 <= NPG)     { g_T4[row0 * H_DIM + c0] = acc00; g_T4[row0 * H_DIM + c0 + 1] = acc01; }
        if (row0 + 1 <= NPG) { g_T4[(row0 + 1) * H_DIM + c0] = acc10; g_T4[(row0 + 1) * H_DIM + c0 + 1] = acc11; }
    } else {
        g_bconst[c0] = acc00 + bo[c0];
        g_bconst[c0 + 1] = acc01 + bo[c0 + 1];
    }
}

// ---------------- W3 transpose + fp16 into B cols 256..767 ----------------
__global__ void k_w3t(const float* __restrict__ Wout) {
    __shared__ float sm[64][65];
    int bx = blockIdx.x, by = blockIdx.y;
    int t = threadIdx.x;
    int lr = t >> 6, lc = t & 63;
    #pragma unroll 4
    for (int j = 0; j < 16; j++) {
        int r = lr * 16 + j;
        sm[r][lc] = Wout[(size_t)(1024 + by * 64 + r) * H_DIM + bx * 64 + lc];
    }
    __syncthreads();
    #pragma unroll 4
    for (int j = 0; j < 16; j++) {
        int nl = lr * 16 + j;
        float v = sm[lc][nl];
        int n = bx * 64 + nl;
        int k = F_DIM + by * 64 + lc;
        g_B[(size_t)n * K_TOT + k] = __float2half(v);
    }
}

// ---------------- bit-parallel BFS ----------------
__global__ void k_bfs() {
    __shared__ unsigned long long adj_sh[NPG];
    int g = blockIdx.x, s = threadIdx.x;
    adj_sh[s] = g_adj[g * NPG + s];
    __syncthreads();
    unsigned long long reach = 1ull << s;
    unsigned long long frontier = reach;
    unsigned char cnt[NPG + 1];
    #pragma unroll
    for (int v = 0; v <= NPG; v++) cnt[v] = 0;
    cnt[0] = 1;
    int maxfin = 0;
    for (int k = 1; k < NPG; k++) {
        unsigned long long nr = 0, f = frontier;
        while (f) {
            int j = __ffsll((long long)f) - 1;
            f &= f - 1;
            nr |= adj_sh[j];
        }
        unsigned long long nxt = nr & ~reach;
        if (!nxt) break;
        cnt[k] = (unsigned char)__popcll(nxt);
        maxfin = k;
        reach |= nxt;
        frontier = nxt;
    }
    int rem = NPG - __popcll(reach);
    cnt[maxfin + 1] = (unsigned char)(cnt[maxfin + 1] + rem);
    unsigned char* h = g_hist + (size_t)(g * NPG + s) * (NPG + 1);
    #pragma unroll
    for (int v = 0; v <= NPG; v++) h[v] = cnt[v];
}

// ---------------- per-node additive vector ----------------
__global__ void k_add() {
    __shared__ int   vlist[NPG + 1];
    __shared__ float clist[NPG + 1];
    __shared__ int   nnz, sdeg;
    int i = blockIdx.x, tid = threadIdx.x;
    if (tid == 0) {
        const unsigned char* h = g_hist + (size_t)i * (NPG + 1);
        int m = 0;
        for (int v = 0; v <= NPG; v++) {
            int c = h[v];
            if (c) { vlist[m] = v; clist[m] = (float)c * (1.0f / 64.0f); m++; }
        }
        nnz = m;
        int d = g_deg[i];
        sdeg = d > MAXDEG ? MAXDEG : d;
    }
    __syncthreads();
    int d = sdeg, m = nnz;
    for (int c0 = tid; c0 < H_DIM; c0 += 128) {
        float a = g_T2[d * H_DIM + c0] + g_bconst[c0];
        for (int j = 0; j < m; j++) a = fmaf(clist[j], g_T4[vlist[j] * H_DIM + c0], a);
        g_add[(size_t)i * H_DIM + c0] = a;
    }
}

// ---------------- HMMA GEMM: D = A @ B^T (fp16), out = D + add ----------------
// CTA tile 128x128, K-chunk 32, 8 warps (2m x 4n), warp tile 64x32.
// smem: per stage 2 planes (A, B) of 128 rows x 80B stride; 4 stages.
#define ROWB        80
#define PLANE_STR   (128 * ROWB)         // 10240
#define STAGE_STR   (2 * PLANE_STR)      // 20480
#define NSTAGE      4
#define GEMM_SMEM   (NSTAGE * STAGE_STR) // 81920
#define NCHUNK      24

__global__ void __launch_bounds__(256, 2) k_gemm(float* __restrict__ out) {
    extern __shared__ char dsm[];
    uint32_t smem = smem_u32(dsm);

    int tid  = threadIdx.x;
    int lane = tid & 31;
    int wid  = tid >> 5;
    int wm   = wid & 1;
    int wn   = wid >> 1;
    int bn = blockIdx.x, bm = blockIdx.y;

    int lrow  = tid >> 1;
    int lhalf = tid & 1;
    const char* srcA = (const char*)(g_A + (size_t)(bm * 128 + lrow) * K_TOT) + lhalf * 32;
    const char* srcB = (const char*)(g_B + (size_t)(bn * 128 + lrow) * K_TOT) + lhalf * 32;
    uint32_t sdst = smem + (uint32_t)lrow * ROWB + (uint32_t)lhalf * 32;

    int q  = lane >> 3, rl = lane & 7;
    uint32_t aoff = (uint32_t)((wm * 64 + 8 * (q & 1) + rl) * ROWB + (8 * (q >> 1)) * 2);
    uint32_t boff = (uint32_t)((wn * 32 + 8 * (q >> 1) + rl) * ROWB + (8 * (q & 1)) * 2);

    float acc[4][4][4];
    #pragma unroll
    for (int a = 0; a < 4; a++)
        #pragma unroll
        for (int b = 0; b < 4; b++)
            #pragma unroll
            for (int e = 0; e < 4; e++) acc[a][b][e] = 0.f;

    // prologue: chunks 0,1,2 into stages 0,1,2
    #pragma unroll
    for (int s = 0; s < 3; s++) {
        uint32_t d = sdst + (uint32_t)s * STAGE_STR;
        cpasync16(d + 0 * PLANE_STR, srcA + s * 64);  cpasync16(d + 0 * PLANE_STR + 16, srcA + s * 64 + 16);
        cpasync16(d + 1 * PLANE_STR, srcB + s * 64);  cpasync16(d + 1 * PLANE_STR + 16, srcB + s * 64 + 16);
        CP_COMMIT();
    }

    for (int c = 0; c < NCHUNK; c++) {
        CP_WAIT2();          // chunk c's group has landed
        __syncthreads();
        if (c + 3 < NCHUNK) {
            uint32_t d = sdst + (uint32_t)((c + 3) & 3) * STAGE_STR;
            const char* oA = srcA + (c + 3) * 64;
            const char* oB = srcB + (c + 3) * 64;
            cpasync16(d + 0 * PLANE_STR, oA);  cpasync16(d + 0 * PLANE_STR + 16, oA + 16);
            cpasync16(d + 1 * PLANE_STR, oB);  cpasync16(d + 1 * PLANE_STR + 16, oB + 16);
        }
        CP_COMMIT();

        uint32_t sA = smem + (uint32_t)(c & 3) * STAGE_STR;
        uint32_t sB = sA + PLANE_STR;

        #pragma unroll
        for (int kk = 0; kk < 2; kk++) {
            uint32_t ah[4][4];
            #pragma unroll
            for (int mf = 0; mf < 4; mf++) {
                uint32_t ad = sA + aoff + (uint32_t)mf * (16 * ROWB) + (uint32_t)kk * 32;
                LDSM4(ah[mf], ad);
            }
            uint32_t bh[2][4];
            #pragma unroll
            for (int nf2 = 0; nf2 < 2; nf2++) {
                uint32_t bd = sB + boff + (uint32_t)nf2 * (16 * ROWB) + (uint32_t)kk * 32;
                LDSM4(bh[nf2], bd);
            }
            #pragma unroll
            for (int mf = 0; mf < 4; mf++) {
                #pragma unroll
                for (int nf = 0; nf < 4; nf++) {
                    int nf2 = nf >> 1, nh = nf & 1;
                    MMA16816(acc[mf][nf], ah[mf], &bh[nf2][nh * 2]);
                }
            }
        }
    }

    // epilogue: out = acc + g_add
    int r0 = bm * 128 + wm * 64 + (lane >> 2);
    int c0 = bn * 128 + wn * 32 + 2 * (lane & 3);
    #pragma unroll
    for (int mf = 0; mf < 4; mf++) {
        #pragma unroll
        for (int nf = 0; nf < 4; nf++) {
            int r = r0 + mf * 16;
            int c = c0 + nf * 8;
            float2 a0 = *(const float2*)&g_add[(size_t)r * H_DIM + c];
            float2 a1 = *(const float2*)&g_add[(size_t)(r + 8) * H_DIM + c];
            float2 o0 = make_float2(acc[mf][nf][0] + a0.x, acc[mf][nf][1] + a0.y);
            float2 o1 = make_float2(acc[mf][nf][2] + a1.x, acc[mf][nf][3] + a1.y);
            *(float2*)&out[(size_t)r * H_DIM + c]       = o0;
            *(float2*)&out[(size_t)(r + 8) * H_DIM + c] = o1;
        }
    }
}

// ---------------- launch ----------------
extern "C" void kernel_launch(void* const* d_in, const int* in_sizes, int n_in,
                              void* d_out, int out_size) {
    const float* x    = (const float*)d_in[0];
    const float* Wf   = (const float*)d_in[1];
    const float* bf   = (const float*)d_in[2];
    const float* Wout = (const float*)d_in[3];
    const float* bo   = (const float*)d_in[4];
    const int*   ei   = (const int*)d_in[5];
    int E = in_sizes[5] / 2;
    float* out = (float*)d_out;

    cudaFuncSetAttribute(k_gemm, cudaFuncAttributeMaxDynamicSharedMemorySize, GEMM_SMEM);

    k_init<<<64, 256>>>();
    k_edges<<<(E + 255) / 256, 256>>>(ei, E);
    k_sc<<<NGRAPH + NPG, 256>>>();
    k_aplanes<<<N_NODES, 256>>>(x);
    k_fold<<<419, 256>>>(Wf, Wout, bf, bo);
    k_w3t<<<dim3(8, 8), 256>>>(Wout);
    k_bfs<<<NGRAPH, NPG>>>();
    k_add<<<N_NODES, 128>>>();
    k_gemm<<<dim3(4, 128), 256, GEMM_SMEM>>>(out);
}

// round 6
// speedup vs baseline: 2.6379x; 1.0482x over previous
#include <cuda_runtime.h>
#include <cuda_fp16.h>
#include <math.h>
#include <stdint.h>

#define N_NODES 16384
#define F_DIM   256
#define H_DIM   512
#define K_TOT   768          // 256 (x) + 512 (pe)
#define NPG     64
#define NGRAPH  256
#define MAXDEG  512

// ---------------- static device scratch ----------------
__device__ __align__(16) __half g_A[N_NODES * K_TOT];   // [x | PE] fp16
__device__ __align__(16) __half g_B[H_DIM * K_TOT];     // B^T: [n][k] fp16
__device__ float g_T2[(MAXDEG + 1) * H_DIM];
__device__ float g_T4[(NPG + 1) * H_DIM];
__device__ float g_bconst[H_DIM];
__device__ __align__(16) __half g_add[N_NODES * H_DIM]; // per-node additive vector (fp16)
__device__ unsigned long long g_adj[N_NODES];
__device__ int g_deg[N_NODES];
__device__ unsigned char g_hist[N_NODES * (NPG + 1)];
__device__ float g_invhi[H_DIM / 2];
__device__ float g_invlo[H_DIM / 2];
__device__ __align__(16) float g_scg[NGRAPH * H_DIM];   // sin/cos(64g * inv_k) pairs
__device__ __align__(16) float g_scr[NPG * H_DIM];      // sin/cos(r * inv_k) pairs

// ---------------- helpers ----------------
__device__ __forceinline__ uint32_t smem_u32(const void* p) {
    uint32_t a;
    asm("{ .reg .u64 t; cvta.to.shared.u64 t, %1; cvt.u32.u64 %0, t; }" : "=r"(a) : "l"(p));
    return a;
}
__device__ __forceinline__ void cpasync16(uint32_t dst, const void* src) {
    asm volatile("cp.async.cg.shared.global [%0], [%1], 16;" :: "r"(dst), "l"(src) : "memory");
}
#define CP_COMMIT() asm volatile("cp.async.commit_group;" ::: "memory")
#define CP_WAIT2()  asm volatile("cp.async.wait_group 2;" ::: "memory")

#define LDSM4(r, addr) \
    asm volatile("ldmatrix.sync.aligned.m8n8.x4.shared.b16 {%0,%1,%2,%3}, [%4];" \
        : "=r"((r)[0]), "=r"((r)[1]), "=r"((r)[2]), "=r"((r)[3]) : "r"(addr))

#define MMA16816(d, a, b) \
    asm volatile("mma.sync.aligned.m16n8k16.row.col.f32.f16.f16.f32 " \
        "{%0,%1,%2,%3}, {%4,%5,%6,%7}, {%8,%9}, {%0,%1,%2,%3};" \
        : "+f"((d)[0]), "+f"((d)[1]), "+f"((d)[2]), "+f"((d)[3]) \
        : "r"((a)[0]), "r"((a)[1]), "r"((a)[2]), "r"((a)[3]), "r"((b)[0]), "r"((b)[1]))

// ---------------- accurate PE angle ----------------
__device__ __forceinline__ void pe_sincos(float pos, int k, float* s, float* c) {
    float hi = g_invhi[k], lo = g_invlo[k];
    float p  = pos * hi;
    float e  = fmaf(pos, hi, -p);
    float al = fmaf(pos, lo, e);
    const float I2PI = 0.15915494309189535f;
    const float P2H  = 6.28318548202514648f;
    const float P2L  = -1.7484855e-7f;
    float q = rintf(p * I2PI);
    float r = fmaf(-q, P2H, p);
    r = fmaf(-q, P2L, r);
    r += al;
    sincosf(r, s, c);
}

// ---------------- init (deg/adj clear + invdiv table) ----------------
__global__ void k_init() {
    int i = blockIdx.x * blockDim.x + threadIdx.x;
    if (i < N_NODES) { g_deg[i] = 0; g_adj[i] = 0ull; }
    if (i < H_DIM / 2) {
        double v = exp(-(double)i * (9.210340371976184 / 256.0));
        float hi = (float)v;
        g_invhi[i] = hi;
        g_invlo[i] = (float)(v - (double)hi);
    }
}

__global__ void k_edges(const int* __restrict__ ei, int E) {
    int e = blockIdx.x * blockDim.x + threadIdx.x;
    if (e >= E) return;
    int u = ei[e], v = ei[E + e];
    atomicAdd(&g_deg[u], 1);
    atomicAdd(&g_deg[v], 1);
    atomicOr(&g_adj[u], 1ull << (v & 63));
    atomicOr(&g_adj[v], 1ull << (u & 63));
}

// ---------------- small sincos tables for the angle-addition identity ----------------
__global__ void k_sc() {
    int b = blockIdx.x, t = threadIdx.x;
    float s, c;
    if (b < NGRAPH) {
        pe_sincos((float)(64 * b), t, &s, &c);
        g_scg[b * H_DIM + 2 * t] = s; g_scg[b * H_DIM + 2 * t + 1] = c;
    } else {
        int r = b - NGRAPH;
        pe_sincos((float)r, t, &s, &c);
        g_scr[r * H_DIM + 2 * t] = s; g_scr[r * H_DIM + 2 * t + 1] = c;
    }
}

// ---------------- A plane: [x | PE(node idx)] -> fp16 (vectorized) ----------------
// 128 threads per node: thread t handles x cols {2t,2t+1} and PE pairs k={2t,2t+1}.
__global__ void k_aplanes(const float* __restrict__ x) {
    int i = blockIdx.x, t = threadIdx.x;
    int g = i >> 6, r = i & 63;
    // x part: float2 -> half2
    float2 xv = *(const float2*)(x + (size_t)i * F_DIM + 2 * t);
    *(__half2*)(g_A + (size_t)i * K_TOT + 2 * t) = __floats2half2_rn(xv.x, xv.y);
    // pe part: two k-pairs via angle addition
    float4 sg = *(const float4*)(g_scg + g * H_DIM + 4 * t);   // (s,c) for k=2t, 2t+1
    float4 sr = *(const float4*)(g_scr + r * H_DIM + 4 * t);
    float s0 = sg.x * sr.y + sg.y * sr.x;
    float c0 = sg.y * sr.y - sg.x * sr.x;
    float s1 = sg.z * sr.w + sg.w * sr.z;
    float c1 = sg.w * sr.w - sg.z * sr.z;
    __half2 p0 = __floats2half2_rn(s0, c0);
    __half2 p1 = __floats2half2_rn(s1, c1);
    uint2 pk = make_uint2(*(uint32_t*)&p0, *(uint32_t*)&p1);
    *(uint2*)(g_A + (size_t)i * K_TOT + F_DIM + 4 * t) = pk;
}

// ---------------- fold: Wc^T (fp16), T2, T4, bconst ----------------
__global__ void k_fold(const float* __restrict__ Wf, const float* __restrict__ Wout,
                       const float* __restrict__ bf, const float* __restrict__ bo) {
    __shared__ float a_sh[2][H_DIM];
    int t = threadIdx.x, b = blockIdx.x;
    int kind, row0;
    const float* B;
    if (b < 128)       { kind = 0; row0 = b * 2;          B = Wout; }
    else if (b < 385)  { kind = 1; row0 = (b - 128) * 2;  B = Wout + 512 * H_DIM; }
    else if (b < 418)  { kind = 2; row0 = (b - 385) * 2;  B = Wout + 1536 * H_DIM; }
    else               { kind = 3; row0 = 0;              B = Wout; }

    if (kind == 0) {
        a_sh[0][t] = Wf[row0 * H_DIM + t];       a_sh[0][t + 256] = Wf[row0 * H_DIM + t + 256];
        a_sh[1][t] = Wf[(row0 + 1) * H_DIM + t]; a_sh[1][t + 256] = Wf[(row0 + 1) * H_DIM + t + 256];
    } else if (kind == 3) {
        a_sh[0][t] = bf[t]; a_sh[0][t + 256] = bf[t + 256];
        a_sh[1][t] = 0.f;   a_sh[1][t + 256] = 0.f;
    } else {
        #pragma unroll
        for (int rr = 0; rr < 2; rr++) {
            float s, c;
            pe_sincos((float)(row0 + rr), t, &s, &c);
            a_sh[rr][2 * t] = s; a_sh[rr][2 * t + 1] = c;
        }
    }
    __syncthreads();

    float acc00 = 0.f, acc01 = 0.f, acc10 = 0.f, acc11 = 0.f;
    const float2* Bp = ((const float2*)B) + t;
    #pragma unroll 4
    for (int h = 0; h < H_DIM; h++) {
        float2 w = Bp[(size_t)h * 256];
        float a0 = a_sh[0][h], a1 = a_sh[1][h];
        acc00 = fmaf(a0, w.x, acc00); acc01 = fmaf(a0, w.y, acc01);
        acc10 = fmaf(a1, w.x, acc10); acc11 = fmaf(a1, w.y, acc11);
    }

    int c0 = 2 * t;
    if (kind == 0) {
        g_B[c0 * K_TOT + row0]           = __float2half(acc00);
        g_B[(c0 + 1) * K_TOT + row0]     = __float2half(acc01);
        g_B[c0 * K_TOT + row0 + 1]       = __float2half(acc10);
        g_B[(c0 + 1) * K_TOT + row0 + 1] = __float2half(acc11);
    } else if (kind == 1) {
        if (row0 <= MAXDEG)     { g_T2[row0 * H_DIM + c0] = acc00; g_T2[row0 * H_DIM + c0 + 1] = acc01; }
        if (row0 + 1 <= MAXDEG) { g_T2[(row0 + 1) * H_DIM + c0] = acc10; g_T2[(row0 + 1) * H_DIM + c0 + 1] = acc11; }
    } else if (kind == 2) {
        if (row0 <= NPG)     { g_T4[row0 * H_DIM + c0] = acc00; g_T4[row0 * H_DIM + c0 + 1] = acc01; }
        if (row0 + 1 <= NPG) { g_T4[(row0 + 1) * H_DIM + c0] = acc10; g_T4[(row0 + 1) * H_DIM + c0 + 1] = acc11; }
    } else {
        g_bconst[c0] = acc00 + bo[c0];
        g_bconst[c0 + 1] = acc01 + bo[c0 + 1];
    }
}

// ---------------- W3 transpose + fp16 into B cols 256..767 ----------------
__global__ void k_w3t(const float* __restrict__ Wout) {
    __shared__ float sm[64][65];
    int bx = blockIdx.x, by = blockIdx.y;
    int t = threadIdx.x;
    int lr = t >> 6, lc = t & 63;
    #pragma unroll 4
    for (int j = 0; j < 16; j++) {
        int r = lr * 16 + j;
        sm[r][lc] = Wout[(size_t)(1024 + by * 64 + r) * H_DIM + bx * 64 + lc];
    }
    __syncthreads();
    #pragma unroll 4
    for (int j = 0; j < 16; j++) {
        int nl = lr * 16 + j;
        float v = sm[lc][nl];
        int n = bx * 64 + nl;
        int k = F_DIM + by * 64 + lc;
        g_B[(size_t)n * K_TOT + k] = __float2half(v);
    }
}

// ---------------- bit-parallel BFS ----------------
__global__ void k_bfs() {
    __shared__ unsigned long long adj_sh[NPG];
    int g = blockIdx.x, s = threadIdx.x;
    adj_sh[s] = g_adj[g * NPG + s];
    __syncthreads();
    unsigned long long reach = 1ull << s;
    unsigned long long frontier = reach;
    unsigned char cnt[NPG + 1];
    #pragma unroll
    for (int v = 0; v <= NPG; v++) cnt[v] = 0;
    cnt[0] = 1;
    int maxfin = 0;
    for (int k = 1; k < NPG; k++) {
        unsigned long long nr = 0, f = frontier;
        while (f) {
            int j = __ffsll((long long)f) - 1;
            f &= f - 1;
            nr |= adj_sh[j];
        }
        unsigned long long nxt = nr & ~reach;
        if (!nxt) break;
        cnt[k] = (unsigned char)__popcll(nxt);
        maxfin = k;
        reach |= nxt;
        frontier = nxt;
    }
    int rem = NPG - __popcll(reach);
    cnt[maxfin + 1] = (unsigned char)(cnt[maxfin + 1] + rem);
    unsigned char* h = g_hist + (size_t)(g * NPG + s) * (NPG + 1);
    #pragma unroll
    for (int v = 0; v <= NPG; v++) h[v] = cnt[v];
}

// ---------------- per-node additive vector (fp16 output) ----------------
__global__ void k_add() {
    __shared__ int   vlist[NPG + 1];
    __shared__ float clist[NPG + 1];
    __shared__ int   nnz, sdeg;
    int i = blockIdx.x, tid = threadIdx.x;
    if (tid == 0) {
        const unsigned char* h = g_hist + (size_t)i * (NPG + 1);
        int m = 0;
        for (int v = 0; v <= NPG; v++) {
            int c = h[v];
            if (c) { vlist[m] = v; clist[m] = (float)c * (1.0f / 64.0f); m++; }
        }
        nnz = m;
        int d = g_deg[i];
        sdeg = d > MAXDEG ? MAXDEG : d;
    }
    __syncthreads();
    int d = sdeg, m = nnz;
    for (int c0 = 2 * tid; c0 < H_DIM; c0 += 256) {
        float a0 = g_T2[d * H_DIM + c0]     + g_bconst[c0];
        float a1 = g_T2[d * H_DIM + c0 + 1] + g_bconst[c0 + 1];
        for (int j = 0; j < m; j++) {
            float cj = clist[j];
            const float* t4 = g_T4 + vlist[j] * H_DIM + c0;
            a0 = fmaf(cj, t4[0], a0);
            a1 = fmaf(cj, t4[1], a1);
        }
        *(__half2*)(g_add + (size_t)i * H_DIM + c0) = __floats2half2_rn(a0, a1);
    }
}

// ---------------- HMMA GEMM: D = A @ B^T (fp16), out = D + add ----------------
// CTA tile 128x128, K-chunk 32, 8 warps (2m x 4n), warp tile 64x32.
// smem: per stage 2 planes (A, B) of 128 rows x 80B stride; 4 stages.
#define ROWB        80
#define PLANE_STR   (128 * ROWB)         // 10240
#define STAGE_STR   (2 * PLANE_STR)      // 20480
#define NSTAGE      4
#define GEMM_SMEM   (NSTAGE * STAGE_STR) // 81920
#define NCHUNK      24

__global__ void __launch_bounds__(256, 2) k_gemm(float* __restrict__ out) {
    extern __shared__ char dsm[];
    uint32_t smem = smem_u32(dsm);

    int tid  = threadIdx.x;
    int lane = tid & 31;
    int wid  = tid >> 5;
    int wm   = wid & 1;
    int wn   = wid >> 1;
    int bn = blockIdx.x, bm = blockIdx.y;

    int lrow  = tid >> 1;
    int lhalf = tid & 1;
    const char* srcA = (const char*)(g_A + (size_t)(bm * 128 + lrow) * K_TOT) + lhalf * 32;
    const char* srcB = (const char*)(g_B + (size_t)(bn * 128 + lrow) * K_TOT) + lhalf * 32;
    uint32_t sdst = smem + (uint32_t)lrow * ROWB + (uint32_t)lhalf * 32;

    int q  = lane >> 3, rl = lane & 7;
    uint32_t aoff = (uint32_t)((wm * 64 + 8 * (q & 1) + rl) * ROWB + (8 * (q >> 1)) * 2);
    uint32_t boff = (uint32_t)((wn * 32 + 8 * (q >> 1) + rl) * ROWB + (8 * (q & 1)) * 2);

    float acc[4][4][4];
    #pragma unroll
    for (int a = 0; a < 4; a++)
        #pragma unroll
        for (int b = 0; b < 4; b++)
            #pragma unroll
            for (int e = 0; e < 4; e++) acc[a][b][e] = 0.f;

    // prologue: chunks 0,1,2 into stages 0,1,2
    #pragma unroll
    for (int s = 0; s < 3; s++) {
        uint32_t d = sdst + (uint32_t)s * STAGE_STR;
        cpasync16(d + 0 * PLANE_STR, srcA + s * 64);  cpasync16(d + 0 * PLANE_STR + 16, srcA + s * 64 + 16);
        cpasync16(d + 1 * PLANE_STR, srcB + s * 64);  cpasync16(d + 1 * PLANE_STR + 16, srcB + s * 64 + 16);
        CP_COMMIT();
    }

    for (int c = 0; c < NCHUNK; c++) {
        CP_WAIT2();          // chunk c's group has landed
        __syncthreads();
        if (c + 3 < NCHUNK) {
            uint32_t d = sdst + (uint32_t)((c + 3) & 3) * STAGE_STR;
            const char* oA = srcA + (c + 3) * 64;
            const char* oB = srcB + (c + 3) * 64;
            cpasync16(d + 0 * PLANE_STR, oA);  cpasync16(d + 0 * PLANE_STR + 16, oA + 16);
            cpasync16(d + 1 * PLANE_STR, oB);  cpasync16(d + 1 * PLANE_STR + 16, oB + 16);
        }
        CP_COMMIT();

        uint32_t sA = smem + (uint32_t)(c & 3) * STAGE_STR;
        uint32_t sB = sA + PLANE_STR;

        #pragma unroll
        for (int kk = 0; kk < 2; kk++) {
            uint32_t ah[4][4];
            #pragma unroll
            for (int mf = 0; mf < 4; mf++) {
                uint32_t ad = sA + aoff + (uint32_t)mf * (16 * ROWB) + (uint32_t)kk * 32;
                LDSM4(ah[mf], ad);
            }
            uint32_t bh[2][4];
            #pragma unroll
            for (int nf2 = 0; nf2 < 2; nf2++) {
                uint32_t bd = sB + boff + (uint32_t)nf2 * (16 * ROWB) + (uint32_t)kk * 32;
                LDSM4(bh[nf2], bd);
            }
            #pragma unroll
            for (int mf = 0; mf < 4; mf++) {
                #pragma unroll
                for (int nf = 0; nf < 4; nf++) {
                    int nf2 = nf >> 1, nh = nf & 1;
                    MMA16816(acc[mf][nf], ah[mf], &bh[nf2][nh * 2]);
                }
            }
        }
    }

    // epilogue: out = acc + g_add (half2 reads)
    int r0 = bm * 128 + wm * 64 + (lane >> 2);
    int c0 = bn * 128 + wn * 32 + 2 * (lane & 3);
    #pragma unroll
    for (int mf = 0; mf < 4; mf++) {
        #pragma unroll
        for (int nf = 0; nf < 4; nf++) {
            int r = r0 + mf * 16;
            int c = c0 + nf * 8;
            __half2 h0 = *(const __half2*)&g_add[(size_t)r * H_DIM + c];
            __half2 h1 = *(const __half2*)&g_add[(size_t)(r + 8) * H_DIM + c];
            float2 a0 = __half22float2(h0);
            float2 a1 = __half22float2(h1);
            float2 o0 = make_float2(acc[mf][nf][0] + a0.x, acc[mf][nf][1] + a0.y);
            float2 o1 = make_float2(acc[mf][nf][2] + a1.x, acc[mf][nf][3] + a1.y);
            *(float2*)&out[(size_t)r * H_DIM + c]       = o0;
            *(float2*)&out[(size_t)(r + 8) * H_DIM + c] = o1;
        }
    }
}

// ---------------- launch ----------------
extern "C" void kernel_launch(void* const* d_in, const int* in_sizes, int n_in,
                              void* d_out, int out_size) {
    const float* x    = (const float*)d_in[0];
    const float* Wf   = (const float*)d_in[1];
    const float* bf   = (const float*)d_in[2];
    const float* Wout = (const float*)d_in[3];
    const float* bo   = (const float*)d_in[4];
    const int*   ei   = (const int*)d_in[5];
    int E = in_sizes[5] / 2;
    float* out = (float*)d_out;

    cudaFuncSetAttribute(k_gemm, cudaFuncAttributeMaxDynamicSharedMemorySize, GEMM_SMEM);

    k_init<<<64, 256>>>();
    k_edges<<<(E + 255) / 256, 256>>>(ei, E);
    k_sc<<<NGRAPH + NPG, 256>>>();
    k_aplanes<<<N_NODES, 128>>>(x);
    k_fold<<<419, 256>>>(Wf, Wout, bf, bo);
    k_w3t<<<dim3(8, 8), 256>>>(Wout);
    k_bfs<<<NGRAPH, NPG>>>();
    k_add<<<N_NODES, 128>>>();
    k_gemm<<<dim3(4, 128), 256, GEMM_SMEM>>>(out);
}